// round 7
// baseline (speedup 1.0000x reference)
#include <cuda_runtime.h>
#include <math.h>

#define BB 8
#define NN 4096
#define DD 768
#define EE 8
#define ES 16
#define FF 3072
#define NTOK (BB*NN)     /* 32768 */
#define PSZ  (NTOK*ES)   /* 524288 */

typedef unsigned long long ull;

/* ---------------- scratch (allocation-free, 16B-aligned) ---------------- */
__device__ __align__(16) float  g_part[3*PSZ];     /* k1 logits partials */
__device__ __align__(16) float  g_logits[PSZ];
__device__ __align__(16) float2 g_cpart[128*16];   /* per-(chunk,slot) combine partials */
__device__ __align__(16) float  g_xsp[256*16*768]; /* k3 partials [b*32+c][slot][d] */
__device__ __align__(16) float  g_h1p[8*EE*ES*FF]; /* k4 partials [dc*8+e][r][f] */
__device__ __align__(16) float  g_ysp[32*EE*ES*DD];/* k5 partials [kc*8+e][r][d] */
__device__ __align__(16) float  g_ys[BB*ES*DD];

/* ---------------- f32x2 helpers ---------------- */
__device__ __forceinline__ ull fma2(ull a, ull b, ull c) {
    ull d; asm("fma.rn.f32x2 %0, %1, %2, %3;" : "=l"(d) : "l"(a), "l"(b), "l"(c)); return d;
}
__device__ __forceinline__ ull dup2(float x) {
    ull r; asm("mov.b64 %0, {%1, %1};" : "=l"(r) : "f"(x)); return r;
}
__device__ __forceinline__ float2 unpack2(ull a) {
    float2 t; asm("mov.b64 {%0, %1}, %2;" : "=f"(t.x), "=f"(t.y) : "l"(a)); return t;
}
__device__ __forceinline__ float gelu_exact(float v) {
    return 0.5f * v * (1.0f + erff(v * 0.70710678118654752440f));
}
__device__ __forceinline__ float warp_max(float v) {
#pragma unroll
    for (int o = 16; o; o >>= 1) v = fmaxf(v, __shfl_xor_sync(0xffffffffu, v, o));
    return v;
}
__device__ __forceinline__ float warp_sum(float v) {
#pragma unroll
    for (int o = 16; o; o >>= 1) v += __shfl_xor_sync(0xffffffffu, v, o);
    return v;
}

/* ================ K1: logits partials  grid(64 tokblocks, 3 kchunks of 256), 256 thr ===== */
__global__ void __launch_bounds__(256) k1_logits(const float* __restrict__ x,
                                                 const float* __restrict__ phi) {
    extern __shared__ float sm[];
    float* xsh = sm;              /* [512][33] pitch-33 */
    float* ph  = sm + 512 * 33;   /* [256][16] */
    const int tid = threadIdx.x;
    const int tokBase = blockIdx.x * 512;
    const int k0 = blockIdx.y * 256;

    for (int i = tid; i < 1024; i += 256)
        ((float4*)ph)[i] = ((const float4*)(phi + (size_t)k0 * ES))[i];

    ull acc[2][8];
#pragma unroll
    for (int p = 0; p < 2; p++)
#pragma unroll
        for (int j = 0; j < 8; j++) acc[p][j] = 0ull;

    for (int sc = 0; sc < 8; sc++) {
        const int kk0 = k0 + sc * 32;
        __syncthreads();
#pragma unroll
        for (int i = 0; i < 16; i++) {
            int idx = tid + 256 * i;
            int t = idx >> 3, q = idx & 7;
            float4 v = *(const float4*)(x + (size_t)(tokBase + t) * DD + kk0 + q * 4);
            float* dst = &xsh[t * 33 + q * 4];   /* scalar STS: pitch-33 alignment */
            dst[0] = v.x; dst[1] = v.y; dst[2] = v.z; dst[3] = v.w;
        }
        __syncthreads();
#pragma unroll 4
        for (int kk = 0; kk < 32; kk++) {
            ull xd0 = dup2(xsh[tid * 33 + kk]);
            ull xd1 = dup2(xsh[(tid + 256) * 33 + kk]);
            const float* pr = &ph[(sc * 32 + kk) * ES];
#pragma unroll
            for (int j = 0; j < 8; j++) {
                ull p2 = *(const ull*)&pr[2 * j];
                acc[0][j] = fma2(xd0, p2, acc[0][j]);
                acc[1][j] = fma2(xd1, p2, acc[1][j]);
            }
        }
    }
    float* outb = g_part + (size_t)blockIdx.y * PSZ;
#pragma unroll
    for (int p = 0; p < 2; p++) {
        int t = tokBase + tid + 256 * p;
        float4* o = (float4*)&outb[(size_t)t * ES];
#pragma unroll
        for (int j2 = 0; j2 < 4; j2++) {
            float2 a = unpack2(acc[p][2 * j2]);
            float2 b = unpack2(acc[p][2 * j2 + 1]);
            o[j2] = make_float4(a.x, a.y, b.x, b.y);
        }
    }
}

/* ================ K2a: sum 3 partials -> logits; combine partial-reduce ===== */
__global__ void __launch_bounds__(256) k2a_dispatch() {
    __shared__ float2 wred[8 * 16];
    const int tid = threadIdx.x;
    const int t = blockIdx.x * 256 + tid;
    const int wid = tid >> 5, lane = tid & 31;
    float v[16];
#pragma unroll
    for (int i = 0; i < 16; i++) v[i] = 0.0f;
#pragma unroll
    for (int c = 0; c < 3; c++) {
        const float4* p = (const float4*)(g_part + (size_t)c * PSZ + (size_t)t * ES);
#pragma unroll
        for (int i = 0; i < 4; i++) {
            float4 a = p[i];
            v[4*i+0] += a.x; v[4*i+1] += a.y; v[4*i+2] += a.z; v[4*i+3] += a.w;
        }
    }
    float4* lo = (float4*)&g_logits[(size_t)t * ES];
#pragma unroll
    for (int i = 0; i < 4; i++)
        lo[i] = make_float4(v[4*i], v[4*i+1], v[4*i+2], v[4*i+3]);
#pragma unroll
    for (int sl = 0; sl < 16; sl++) {
        float wm = warp_max(v[sl]);
        float ws = warp_sum(expf(v[sl] - wm));
        if (lane == 0) wred[wid * 16 + sl] = make_float2(wm, ws);
    }
    __syncthreads();
    if (tid < 16) {
        float gm = -1e30f;
#pragma unroll
        for (int w = 0; w < 8; w++) gm = fmaxf(gm, wred[w * 16 + tid].x);
        float gs = 0.0f;
#pragma unroll
        for (int w = 0; w < 8; w++) {
            float2 p = wred[w * 16 + tid];
            gs += expf(p.x - gm) * p.y;
        }
        g_cpart[blockIdx.x * 16 + tid] = make_float2(gm, gs);
    }
}

/* ================ K3: xs partials, dispatch softmax inline  grid(32,8), 192 thr ===== */
__global__ void __launch_bounds__(192) k3_xs(const float* __restrict__ x) {
    __shared__ float2 dsh[128 * 16];
    const int chunk = blockIdx.x, b = blockIdx.y, tid = threadIdx.x;
    const int n0 = chunk * 128;
    if (tid < 128) {
        const float4* lp = (const float4*)&g_logits[(size_t)(b * NN + n0 + tid) * ES];
        float v[16];
#pragma unroll
        for (int i = 0; i < 4; i++) {
            float4 a = lp[i];
            v[4*i] = a.x; v[4*i+1] = a.y; v[4*i+2] = a.z; v[4*i+3] = a.w;
        }
        float m = v[0];
#pragma unroll
        for (int i = 1; i < 16; i++) m = fmaxf(m, v[i]);
        float ex[16], s = 0.0f;
#pragma unroll
        for (int i = 0; i < 16; i++) { ex[i] = expf(v[i] - m); s += ex[i]; }
        float inv = 1.0f / s;
        float2* dr = &dsh[tid * 16];
#pragma unroll
        for (int i = 0; i < 16; i++) { float w = ex[i] * inv; dr[i] = make_float2(w, w); }
    }
    __syncthreads();
    ull acc[16][2];
#pragma unroll
    for (int s = 0; s < 16; s++) { acc[s][0] = 0ull; acc[s][1] = 0ull; }
    const float* xb = x + (size_t)(b * NN + n0) * DD + tid * 4;
    for (int g = 0; g < 128; g += 8) {
        float4 xv[8];
#pragma unroll
        for (int u = 0; u < 8; u++) xv[u] = *(const float4*)(xb + (size_t)(g + u) * DD);
#pragma unroll
        for (int u = 0; u < 8; u++) {
            ull l = *(ull*)&xv[u].x, h = *(ull*)&xv[u].z;
            const float2* dr = &dsh[(g + u) * 16];
#pragma unroll
            for (int s = 0; s < 16; s++) {
                ull c = *(const ull*)&dr[s];
                acc[s][0] = fma2(c, l, acc[s][0]);
                acc[s][1] = fma2(c, h, acc[s][1]);
            }
        }
    }
    float* op = g_xsp + (size_t)(b * 32 + chunk) * 16 * DD + tid * 4;
#pragma unroll
    for (int s = 0; s < 16; s++) {
        float2 a = unpack2(acc[s][0]), c = unpack2(acc[s][1]);
        *(float4*)(op + (size_t)s * DD) = make_float4(a.x, a.y, c.x, c.y);
    }
}

/* ================ K4: FFN1, staging folds the 32-chunk xs reduction
   grid(3 ftiles, 8 e, 8 dchunks), 256 thr ===== */
__global__ void __launch_bounds__(256) k4_ffn1(const float* __restrict__ w1) {
    __shared__ float2 xd[16][100];    /* [r][ddv] dup-pairs, padded */
    const int ft = blockIdx.x, e = blockIdx.y, dc = blockIdx.z, tid = threadIdx.x;
    const int dk0 = dc * 96;
    for (int i = tid; i < 1536; i += 256) {
        int r = i / 96, ddv = i - r * 96;    /* warp spans consecutive ddv -> coalesced */
        const float* p = g_xsp + ((size_t)((r >> 1) * 32) * 16 + e * 2 + (r & 1)) * DD
                       + dk0 + ddv;
        float s = 0.0f;
#pragma unroll
        for (int cb = 0; cb < 2; cb++) {
            float tv[16];
#pragma unroll
            for (int c = 0; c < 16; c++) tv[c] = p[(size_t)(cb * 16 + c) * (16 * DD)];
#pragma unroll
            for (int c = 0; c < 16; c++) s += tv[c];
        }
        xd[r][ddv] = make_float2(s, s);
    }
    __syncthreads();
    const int f = ft * 1024 + tid * 4;
    const float* wp = w1 + (size_t)e * DD * FF + (size_t)dk0 * FF + f;
    ull acc[16][2];
#pragma unroll
    for (int r = 0; r < 16; r++) { acc[r][0] = 0ull; acc[r][1] = 0ull; }
    for (int d = 0; d < 96; d += 8) {
        float4 wv[8];
#pragma unroll
        for (int u = 0; u < 8; u++) wv[u] = *(const float4*)(wp + (size_t)(d + u) * FF);
#pragma unroll
        for (int u = 0; u < 8; u++) {
            ull l = *(ull*)&wv[u].x, h = *(ull*)&wv[u].z;
#pragma unroll
            for (int r = 0; r < 16; r++) {
                ull c = *(const ull*)&xd[r][d + u];
                acc[r][0] = fma2(c, l, acc[r][0]);
                acc[r][1] = fma2(c, h, acc[r][1]);
            }
        }
    }
    float* op = g_h1p + (size_t)(dc * 8 + e) * 16 * FF + f;
#pragma unroll
    for (int r = 0; r < 16; r++) {
        float2 a = unpack2(acc[r][0]), c = unpack2(acc[r][1]);
        *(float4*)(op + (size_t)r * FF) = make_float4(a.x, a.y, c.x, c.y);
    }
}

/* ================ K5: FFN2, staging folds 8-chunk h reduction + bias + gelu
   grid(32 kchunks of 96, 8 e), 192 thr ===== */
__global__ void __launch_bounds__(192) k5_ffn2(const float* __restrict__ w2,
                                               const float* __restrict__ b1) {
    __shared__ float2 hd[16][100];    /* [r][kk] dup-pairs, padded */
    const int kc = blockIdx.x, e = blockIdx.y, tid = threadIdx.x;
    const int k0 = kc * 96;
    for (int i = tid; i < 1536; i += 192) {
        int r = i / 96, kk = i - r * 96;     /* warp spans consecutive kk -> coalesced */
        int fidx = k0 + kk;
        const float* p = g_h1p + ((size_t)e * 16 + r) * FF + fidx;
        float s = 0.0f;
        float tv[8];
#pragma unroll
        for (int c = 0; c < 8; c++) tv[c] = p[(size_t)c * (8 * 16 * FF)];
#pragma unroll
        for (int c = 0; c < 8; c++) s += tv[c];
        s = gelu_exact(s + b1[e * FF + fidx]);
        hd[r][kk] = make_float2(s, s);
    }
    __syncthreads();
    const int d4 = tid * 4;
    const float* wp = w2 + (size_t)e * FF * DD + (size_t)k0 * DD + d4;
    ull acc[16][2];
#pragma unroll
    for (int r = 0; r < 16; r++) { acc[r][0] = 0ull; acc[r][1] = 0ull; }
    for (int kk = 0; kk < 96; kk += 8) {
        float4 wv[8];
#pragma unroll
        for (int u = 0; u < 8; u++) wv[u] = *(const float4*)(wp + (size_t)(kk + u) * DD);
#pragma unroll
        for (int u = 0; u < 8; u++) {
            ull l = *(ull*)&wv[u].x, h = *(ull*)&wv[u].z;
#pragma unroll
            for (int r = 0; r < 16; r++) {
                ull c = *(const ull*)&hd[r][kk + u];
                acc[r][0] = fma2(c, l, acc[r][0]);
                acc[r][1] = fma2(c, h, acc[r][1]);
            }
        }
    }
    float* op = g_ysp + (size_t)(kc * 8 + e) * 16 * DD + d4;
#pragma unroll
    for (int r = 0; r < 16; r++) {
        float2 a = unpack2(acc[r][0]), c = unpack2(acc[r][1]);
        *(float4*)(op + (size_t)r * DD) = make_float4(a.x, a.y, c.x, c.y);
    }
}

/* ================ K5r: reduce 32 kchunks + bias -> g_ys  grid(192), 256 thr ===== */
__global__ void __launch_bounds__(256) k5r_reduce(const float* __restrict__ b2) {
    int o2 = blockIdx.x * 256 + threadIdx.x;    /* 49152 float2 outputs */
    int d2 = o2 % 384, rest = o2 / 384;
    int sl = rest & 15, b = rest >> 4;
    int e = sl >> 1;
    int r = b * 2 + (sl & 1);
    const float2* p = (const float2*)(g_ysp + ((size_t)e * 16 + r) * DD) + d2;
    float sx = 0.f, sy = 0.f;
#pragma unroll
    for (int cb = 0; cb < 2; cb++) {
        float2 tv[16];
#pragma unroll
        for (int c = 0; c < 16; c++)
            tv[c] = p[(size_t)(cb * 16 + c) * (8 * 16 * 384)];
#pragma unroll
        for (int c = 0; c < 16; c++) { sx += tv[c].x; sy += tv[c].y; }
    }
    float2 bv = ((const float2*)b2)[e * 384 + d2];
    ((float2*)g_ys)[(size_t)(b * 16 + sl) * 384 + d2] = make_float2(sx + bv.x, sy + bv.y);
}

/* ================ K6: combine norm + y = comb @ ys  grid(64,8), 256 thr ===== */
__global__ void __launch_bounds__(256) k6_out(float* __restrict__ y) {
    __shared__ float2 cms_sh[16];
    __shared__ float csh[64 * ES];
    const int chunk = blockIdx.x, b = blockIdx.y, tid = threadIdx.x;
    ull ysr[8][3];
#pragma unroll
    for (int j = 0; j < 8; j++)
#pragma unroll
        for (int dd = 0; dd < 3; dd++) {
            int d = tid + 256 * dd;
            float a = g_ys[(size_t)(b * 16 + 2 * j) * DD + d];
            float c = g_ys[(size_t)(b * 16 + 2 * j + 1) * DD + d];
            ull r; asm("mov.b64 %0, {%1, %2};" : "=l"(r) : "f"(a), "f"(c));
            ysr[j][dd] = r;
        }
    if (tid < 16) {
        float gm = -1e30f;
#pragma unroll
        for (int c = 0; c < 16; c++) gm = fmaxf(gm, g_cpart[(b * 16 + c) * 16 + tid].x);
        float gs = 0.0f;
#pragma unroll
        for (int c = 0; c < 16; c++) {
            float2 p = g_cpart[(b * 16 + c) * 16 + tid];
            gs += expf(p.x - gm) * p.y;
        }
        cms_sh[tid] = make_float2(gm, 1.0f / gs);
    }
    ((float4*)csh)[tid] = ((const float4*)&g_logits[(size_t)(b * NN + chunk * 64) * ES])[tid];
    __syncthreads();
    {
        int sl = (tid * 4) & 15;
        float4 v = ((float4*)csh)[tid];
        v.x = expf(v.x - cms_sh[sl+0].x) * cms_sh[sl+0].y;
        v.y = expf(v.y - cms_sh[sl+1].x) * cms_sh[sl+1].y;
        v.z = expf(v.z - cms_sh[sl+2].x) * cms_sh[sl+2].y;
        v.w = expf(v.w - cms_sh[sl+3].x) * cms_sh[sl+3].y;
        __syncthreads();
        ((float4*)csh)[tid] = v;
    }
    __syncthreads();
#pragma unroll 2
    for (int tok = 0; tok < 64; tok++) {
        ull c2[8];
#pragma unroll
        for (int j = 0; j < 8; j++) c2[j] = *(const ull*)&csh[tok * ES + 2 * j];
        float* yo = y + (size_t)(b * NN + chunk * 64 + tok) * DD + tid;
#pragma unroll
        for (int dd = 0; dd < 3; dd++) {
            ull a = 0ull;
#pragma unroll
            for (int j = 0; j < 8; j++) a = fma2(c2[j], ysr[j][dd], a);
            float2 t = unpack2(a);
            yo[256 * dd] = t.x + t.y;
        }
    }
}

/* ---------------- launch ---------------- */
extern "C" void kernel_launch(void* const* d_in, const int* in_sizes, int n_in,
                              void* d_out, int out_size) {
    const float* x   = (const float*)d_in[0];
    const float* phi = (const float*)d_in[1];
    const float* w1  = (const float*)d_in[2];
    const float* b1  = (const float*)d_in[3];
    const float* w2  = (const float*)d_in[4];
    const float* b2  = (const float*)d_in[5];
    float* y = (float*)d_out;

    cudaFuncSetAttribute(k1_logits, cudaFuncAttributeMaxDynamicSharedMemorySize, 86016);

    k1_logits<<<dim3(64, 3), 256, 83968>>>(x, phi);
    k2a_dispatch<<<128, 256>>>();
    k3_xs<<<dim3(32, 8), 192>>>(x);
    k4_ffn1<<<dim3(3, 8, 8), 256>>>(w1);
    k5_ffn2<<<dim3(32, 8), 192>>>(w2, b1);
    k5r_reduce<<<192, 256>>>(b2);
    k6_out<<<dim3(64, 8), 256>>>(y);
}

// round 8
// speedup vs baseline: 1.0497x; 1.0497x over previous
#include <cuda_runtime.h>
#include <math.h>

#define BB 8
#define NN 4096
#define DD 768
#define EE 8
#define ES 16
#define FF 3072
#define NTOK (BB*NN)     /* 32768 */
#define PSZ  (NTOK*ES)   /* 524288 */

typedef unsigned long long ull;

/* ---------------- scratch (allocation-free, 16B-aligned) ---------------- */
__device__ __align__(16) float  g_part[3*PSZ];     /* k1 logits partials */
__device__ __align__(16) float  g_logits[PSZ];
__device__ __align__(16) float2 g_cpart[128*16];   /* per-(chunk,slot) combine partials */
__device__ __align__(16) float  g_xsp[256*16*768]; /* k3 partials [b*32+c][slot][d] */
__device__ __align__(16) float  g_h1p[8*EE*ES*FF]; /* k4 partials [dc*8+e][r][f] */
__device__ __align__(16) float  g_ysp[32*EE*ES*DD];/* k5 partials [kc*8+e][r][d] */
__device__ __align__(16) float  g_ys[BB*ES*DD];

/* ---------------- f32x2 helpers ---------------- */
__device__ __forceinline__ ull fma2(ull a, ull b, ull c) {
    ull d; asm("fma.rn.f32x2 %0, %1, %2, %3;" : "=l"(d) : "l"(a), "l"(b), "l"(c)); return d;
}
__device__ __forceinline__ ull dup2(float x) {
    ull r; asm("mov.b64 %0, {%1, %1};" : "=l"(r) : "f"(x)); return r;
}
__device__ __forceinline__ float2 unpack2(ull a) {
    float2 t; asm("mov.b64 {%0, %1}, %2;" : "=f"(t.x), "=f"(t.y) : "l"(a)); return t;
}
__device__ __forceinline__ float gelu_exact(float v) {
    return 0.5f * v * (1.0f + erff(v * 0.70710678118654752440f));
}
__device__ __forceinline__ float warp_max(float v) {
#pragma unroll
    for (int o = 16; o; o >>= 1) v = fmaxf(v, __shfl_xor_sync(0xffffffffu, v, o));
    return v;
}
__device__ __forceinline__ float warp_sum(float v) {
#pragma unroll
    for (int o = 16; o; o >>= 1) v += __shfl_xor_sync(0xffffffffu, v, o);
    return v;
}

/* ================ K1: logits partials  grid(64 tokblocks, 3 kchunks of 256), 256 thr ===== */
__global__ void __launch_bounds__(256) k1_logits(const float* __restrict__ x,
                                                 const float* __restrict__ phi) {
    extern __shared__ float sm[];
    float* xsh = sm;              /* [512][33] pitch-33 */
    float* ph  = sm + 512 * 33;   /* [256][16] */
    const int tid = threadIdx.x;
    const int tokBase = blockIdx.x * 512;
    const int k0 = blockIdx.y * 256;

    for (int i = tid; i < 1024; i += 256)
        ((float4*)ph)[i] = ((const float4*)(phi + (size_t)k0 * ES))[i];

    ull acc[2][8];
#pragma unroll
    for (int p = 0; p < 2; p++)
#pragma unroll
        for (int j = 0; j < 8; j++) acc[p][j] = 0ull;

    for (int sc = 0; sc < 8; sc++) {
        const int kk0 = k0 + sc * 32;
        __syncthreads();
#pragma unroll
        for (int i = 0; i < 16; i++) {
            int idx = tid + 256 * i;
            int t = idx >> 3, q = idx & 7;
            float4 v = *(const float4*)(x + (size_t)(tokBase + t) * DD + kk0 + q * 4);
            float* dst = &xsh[t * 33 + q * 4];   /* scalar STS: pitch-33 alignment */
            dst[0] = v.x; dst[1] = v.y; dst[2] = v.z; dst[3] = v.w;
        }
        __syncthreads();
#pragma unroll 4
        for (int kk = 0; kk < 32; kk++) {
            ull xd0 = dup2(xsh[tid * 33 + kk]);
            ull xd1 = dup2(xsh[(tid + 256) * 33 + kk]);
            const float* pr = &ph[(sc * 32 + kk) * ES];
#pragma unroll
            for (int j = 0; j < 8; j++) {
                ull p2 = *(const ull*)&pr[2 * j];
                acc[0][j] = fma2(xd0, p2, acc[0][j]);
                acc[1][j] = fma2(xd1, p2, acc[1][j]);
            }
        }
    }
    float* outb = g_part + (size_t)blockIdx.y * PSZ;
#pragma unroll
    for (int p = 0; p < 2; p++) {
        int t = tokBase + tid + 256 * p;
        float4* o = (float4*)&outb[(size_t)t * ES];
#pragma unroll
        for (int j2 = 0; j2 < 4; j2++) {
            float2 a = unpack2(acc[p][2 * j2]);
            float2 b = unpack2(acc[p][2 * j2 + 1]);
            o[j2] = make_float4(a.x, a.y, b.x, b.y);
        }
    }
}

/* ================ K2a: sum 3 partials -> logits; combine partial-reduce ===== */
__global__ void __launch_bounds__(256) k2a_dispatch() {
    __shared__ float2 wred[8 * 16];
    const int tid = threadIdx.x;
    const int t = blockIdx.x * 256 + tid;
    const int wid = tid >> 5, lane = tid & 31;
    float v[16];
#pragma unroll
    for (int i = 0; i < 16; i++) v[i] = 0.0f;
#pragma unroll
    for (int c = 0; c < 3; c++) {
        const float4* p = (const float4*)(g_part + (size_t)c * PSZ + (size_t)t * ES);
#pragma unroll
        for (int i = 0; i < 4; i++) {
            float4 a = p[i];
            v[4*i+0] += a.x; v[4*i+1] += a.y; v[4*i+2] += a.z; v[4*i+3] += a.w;
        }
    }
    float4* lo = (float4*)&g_logits[(size_t)t * ES];
#pragma unroll
    for (int i = 0; i < 4; i++)
        lo[i] = make_float4(v[4*i], v[4*i+1], v[4*i+2], v[4*i+3]);
#pragma unroll
    for (int sl = 0; sl < 16; sl++) {
        float wm = warp_max(v[sl]);
        float ws = warp_sum(expf(v[sl] - wm));
        if (lane == 0) wred[wid * 16 + sl] = make_float2(wm, ws);
    }
    __syncthreads();
    if (tid < 16) {
        float gm = -1e30f;
#pragma unroll
        for (int w = 0; w < 8; w++) gm = fmaxf(gm, wred[w * 16 + tid].x);
        float gs = 0.0f;
#pragma unroll
        for (int w = 0; w < 8; w++) {
            float2 p = wred[w * 16 + tid];
            gs += expf(p.x - gm) * p.y;
        }
        g_cpart[blockIdx.x * 16 + tid] = make_float2(gm, gs);
    }
}

/* ================ K3: xs partials, dispatch softmax inline  grid(32,8), 192 thr ===== */
__global__ void __launch_bounds__(192) k3_xs(const float* __restrict__ x) {
    __shared__ float2 dsh[128 * 16];
    const int chunk = blockIdx.x, b = blockIdx.y, tid = threadIdx.x;
    const int n0 = chunk * 128;
    if (tid < 128) {
        const float4* lp = (const float4*)&g_logits[(size_t)(b * NN + n0 + tid) * ES];
        float v[16];
#pragma unroll
        for (int i = 0; i < 4; i++) {
            float4 a = lp[i];
            v[4*i] = a.x; v[4*i+1] = a.y; v[4*i+2] = a.z; v[4*i+3] = a.w;
        }
        float m = v[0];
#pragma unroll
        for (int i = 1; i < 16; i++) m = fmaxf(m, v[i]);
        float ex[16], s = 0.0f;
#pragma unroll
        for (int i = 0; i < 16; i++) { ex[i] = expf(v[i] - m); s += ex[i]; }
        float inv = 1.0f / s;
        float2* dr = &dsh[tid * 16];
#pragma unroll
        for (int i = 0; i < 16; i++) { float w = ex[i] * inv; dr[i] = make_float2(w, w); }
    }
    __syncthreads();
    ull acc[16][2];
#pragma unroll
    for (int s = 0; s < 16; s++) { acc[s][0] = 0ull; acc[s][1] = 0ull; }
    const float* xb = x + (size_t)(b * NN + n0) * DD + tid * 4;
    for (int g = 0; g < 128; g += 8) {
        float4 xv[8];
#pragma unroll
        for (int u = 0; u < 8; u++) xv[u] = *(const float4*)(xb + (size_t)(g + u) * DD);
#pragma unroll
        for (int u = 0; u < 8; u++) {
            ull l = *(ull*)&xv[u].x, h = *(ull*)&xv[u].z;
            const float2* dr = &dsh[(g + u) * 16];
#pragma unroll
            for (int s = 0; s < 16; s++) {
                ull c = *(const ull*)&dr[s];
                acc[s][0] = fma2(c, l, acc[s][0]);
                acc[s][1] = fma2(c, h, acc[s][1]);
            }
        }
    }
    float* op = g_xsp + (size_t)(b * 32 + chunk) * 16 * DD + tid * 4;
#pragma unroll
    for (int s = 0; s < 16; s++) {
        float2 a = unpack2(acc[s][0]), c = unpack2(acc[s][1]);
        *(float4*)(op + (size_t)s * DD) = make_float4(a.x, a.y, c.x, c.y);
    }
}

/* ================ K4: FFN1, staging folds the 32-chunk xs reduction
   grid(6 ftiles of 512, 8 e, 8 dchunks), 128 thr, 4 CTAs/SM ===== */
__global__ void __launch_bounds__(128, 4) k4_ffn1(const float* __restrict__ w1) {
    __shared__ float2 xd[16][104];    /* [r][ddv] dup-pairs, pitch 832B (16B-mult) */
    const int ft = blockIdx.x, e = blockIdx.y, dc = blockIdx.z, tid = threadIdx.x;
    const int dk0 = dc * 96;
    for (int i = tid; i < 1536; i += 128) {
        int r = i / 96, ddv = i - r * 96;
        const float* p = g_xsp + ((size_t)((r >> 1) * 32) * 16 + e * 2 + (r & 1)) * DD
                       + dk0 + ddv;
        float s = 0.0f;
#pragma unroll
        for (int cb = 0; cb < 2; cb++) {
            float tv[16];
#pragma unroll
            for (int c = 0; c < 16; c++) tv[c] = p[(size_t)(cb * 16 + c) * (16 * DD)];
#pragma unroll
            for (int c = 0; c < 16; c++) s += tv[c];
        }
        xd[r][ddv] = make_float2(s, s);
    }
    __syncthreads();
    const int f = ft * 512 + tid * 4;
    const float* wp = w1 + (size_t)e * DD * FF + (size_t)dk0 * FF + f;
    ull acc[16][2];
#pragma unroll
    for (int r = 0; r < 16; r++) { acc[r][0] = 0ull; acc[r][1] = 0ull; }
    for (int d = 0; d < 96; d += 8) {
        float4 wv[8];
#pragma unroll
        for (int u = 0; u < 8; u++) wv[u] = *(const float4*)(wp + (size_t)(d + u) * FF);
#pragma unroll
        for (int r = 0; r < 16; r++) {
#pragma unroll
            for (int q = 0; q < 4; q++) {
                float4 xq = *(const float4*)&xd[r][d + 2 * q];   /* broadcast LDS.128 */
                ull c0 = *(ull*)&xq.x, c1 = *(ull*)&xq.z;
                acc[r][0] = fma2(c0, *(ull*)&wv[2*q].x,   acc[r][0]);
                acc[r][1] = fma2(c0, *(ull*)&wv[2*q].z,   acc[r][1]);
                acc[r][0] = fma2(c1, *(ull*)&wv[2*q+1].x, acc[r][0]);
                acc[r][1] = fma2(c1, *(ull*)&wv[2*q+1].z, acc[r][1]);
            }
        }
    }
    float* op = g_h1p + (size_t)(dc * 8 + e) * 16 * FF + f;
#pragma unroll
    for (int r = 0; r < 16; r++) {
        float2 a = unpack2(acc[r][0]), c = unpack2(acc[r][1]);
        *(float4*)(op + (size_t)r * FF) = make_float4(a.x, a.y, c.x, c.y);
    }
}

/* ================ K5: FFN2, staging folds 8-chunk h reduction + bias + gelu
   grid(32 kchunks of 96, 8 e, 2 dtiles of 384), 96 thr, 5 CTAs/SM ===== */
__global__ void __launch_bounds__(96, 5) k5_ffn2(const float* __restrict__ w2,
                                                 const float* __restrict__ b1) {
    __shared__ float2 hd[16][104];    /* [r][kk] dup-pairs, pitch 832B */
    const int kc = blockIdx.x, e = blockIdx.y, dt = blockIdx.z, tid = threadIdx.x;
    const int k0 = kc * 96;
    for (int i = tid; i < 1536; i += 96) {
        int r = i / 96, kk = i - r * 96;
        int fidx = k0 + kk;
        const float* p = g_h1p + ((size_t)e * 16 + r) * FF + fidx;
        float s = 0.0f;
        float tv[8];
#pragma unroll
        for (int c = 0; c < 8; c++) tv[c] = p[(size_t)c * (8 * 16 * FF)];
#pragma unroll
        for (int c = 0; c < 8; c++) s += tv[c];
        s = gelu_exact(s + b1[e * FF + fidx]);
        hd[r][kk] = make_float2(s, s);
    }
    __syncthreads();
    const int d = dt * 384 + tid * 4;
    const float* wp = w2 + (size_t)e * FF * DD + (size_t)k0 * DD + d;
    ull acc[16][2];
#pragma unroll
    for (int r = 0; r < 16; r++) { acc[r][0] = 0ull; acc[r][1] = 0ull; }
    for (int kk = 0; kk < 96; kk += 8) {
        float4 wv[8];
#pragma unroll
        for (int u = 0; u < 8; u++) wv[u] = *(const float4*)(wp + (size_t)(kk + u) * DD);
#pragma unroll
        for (int r = 0; r < 16; r++) {
#pragma unroll
            for (int q = 0; q < 4; q++) {
                float4 xq = *(const float4*)&hd[r][kk + 2 * q];  /* broadcast LDS.128 */
                ull c0 = *(ull*)&xq.x, c1 = *(ull*)&xq.z;
                acc[r][0] = fma2(c0, *(ull*)&wv[2*q].x,   acc[r][0]);
                acc[r][1] = fma2(c0, *(ull*)&wv[2*q].z,   acc[r][1]);
                acc[r][0] = fma2(c1, *(ull*)&wv[2*q+1].x, acc[r][0]);
                acc[r][1] = fma2(c1, *(ull*)&wv[2*q+1].z, acc[r][1]);
            }
        }
    }
    float* op = g_ysp + (size_t)(kc * 8 + e) * 16 * DD + d;
#pragma unroll
    for (int r = 0; r < 16; r++) {
        float2 a = unpack2(acc[r][0]), c = unpack2(acc[r][1]);
        *(float4*)(op + (size_t)r * DD) = make_float4(a.x, a.y, c.x, c.y);
    }
}

/* ================ K5r: reduce 32 kchunks + bias -> g_ys  grid(192), 256 thr ===== */
__global__ void __launch_bounds__(256) k5r_reduce(const float* __restrict__ b2) {
    int o2 = blockIdx.x * 256 + threadIdx.x;    /* 49152 float2 outputs */
    int d2 = o2 % 384, rest = o2 / 384;
    int sl = rest & 15, b = rest >> 4;
    int e = sl >> 1;
    int r = b * 2 + (sl & 1);
    const float2* p = (const float2*)(g_ysp + ((size_t)e * 16 + r) * DD) + d2;
    float sx = 0.f, sy = 0.f;
#pragma unroll
    for (int cb = 0; cb < 2; cb++) {
        float2 tv[16];
#pragma unroll
        for (int c = 0; c < 16; c++)
            tv[c] = p[(size_t)(cb * 16 + c) * (8 * 16 * 384)];
#pragma unroll
        for (int c = 0; c < 16; c++) { sx += tv[c].x; sy += tv[c].y; }
    }
    float2 bv = ((const float2*)b2)[e * 384 + d2];
    ((float2*)g_ys)[(size_t)(b * 16 + sl) * 384 + d2] = make_float2(sx + bv.x, sy + bv.y);
}

/* ================ K6: combine norm + y = comb @ ys  grid(64,8), 256 thr ===== */
__global__ void __launch_bounds__(256) k6_out(float* __restrict__ y) {
    __shared__ float2 cms_sh[16];
    __shared__ float csh[64 * ES];
    const int chunk = blockIdx.x, b = blockIdx.y, tid = threadIdx.x;
    ull ysr[8][3];
#pragma unroll
    for (int j = 0; j < 8; j++)
#pragma unroll
        for (int dd = 0; dd < 3; dd++) {
            int d = tid + 256 * dd;
            float a = g_ys[(size_t)(b * 16 + 2 * j) * DD + d];
            float c = g_ys[(size_t)(b * 16 + 2 * j + 1) * DD + d];
            ull r; asm("mov.b64 %0, {%1, %2};" : "=l"(r) : "f"(a), "f"(c));
            ysr[j][dd] = r;
        }
    if (tid < 16) {
        float gm = -1e30f;
#pragma unroll
        for (int c = 0; c < 16; c++) gm = fmaxf(gm, g_cpart[(b * 16 + c) * 16 + tid].x);
        float gs = 0.0f;
#pragma unroll
        for (int c = 0; c < 16; c++) {
            float2 p = g_cpart[(b * 16 + c) * 16 + tid];
            gs += expf(p.x - gm) * p.y;
        }
        cms_sh[tid] = make_float2(gm, 1.0f / gs);
    }
    ((float4*)csh)[tid] = ((const float4*)&g_logits[(size_t)(b * NN + chunk * 64) * ES])[tid];
    __syncthreads();
    {
        int sl = (tid * 4) & 15;
        float4 v = ((float4*)csh)[tid];
        v.x = expf(v.x - cms_sh[sl+0].x) * cms_sh[sl+0].y;
        v.y = expf(v.y - cms_sh[sl+1].x) * cms_sh[sl+1].y;
        v.z = expf(v.z - cms_sh[sl+2].x) * cms_sh[sl+2].y;
        v.w = expf(v.w - cms_sh[sl+3].x) * cms_sh[sl+3].y;
        __syncthreads();
        ((float4*)csh)[tid] = v;
    }
    __syncthreads();
#pragma unroll 2
    for (int tok = 0; tok < 64; tok++) {
        ull c2[8];
#pragma unroll
        for (int j = 0; j < 8; j++) c2[j] = *(const ull*)&csh[tok * ES + 2 * j];
        float* yo = y + (size_t)(b * NN + chunk * 64 + tok) * DD + tid;
#pragma unroll
        for (int dd = 0; dd < 3; dd++) {
            ull a = 0ull;
#pragma unroll
            for (int j = 0; j < 8; j++) a = fma2(c2[j], ysr[j][dd], a);
            float2 t = unpack2(a);
            yo[256 * dd] = t.x + t.y;
        }
    }
}

/* ---------------- launch ---------------- */
extern "C" void kernel_launch(void* const* d_in, const int* in_sizes, int n_in,
                              void* d_out, int out_size) {
    const float* x   = (const float*)d_in[0];
    const float* phi = (const float*)d_in[1];
    const float* w1  = (const float*)d_in[2];
    const float* b1  = (const float*)d_in[3];
    const float* w2  = (const float*)d_in[4];
    const float* b2  = (const float*)d_in[5];
    float* y = (float*)d_out;

    cudaFuncSetAttribute(k1_logits, cudaFuncAttributeMaxDynamicSharedMemorySize, 86016);

    k1_logits<<<dim3(64, 3), 256, 83968>>>(x, phi);
    k2a_dispatch<<<128, 256>>>();
    k3_xs<<<dim3(32, 8), 192>>>(x);
    k4_ffn1<<<dim3(6, 8, 8), 128>>>(w1);
    k5_ffn2<<<dim3(32, 8, 2), 96>>>(w2, b1);
    k5r_reduce<<<192, 256>>>(b2);
    k6_out<<<dim3(64, 8), 256>>>(y);
}

// round 9
// speedup vs baseline: 1.1420x; 1.0879x over previous
#include <cuda_runtime.h>
#include <math.h>

#define BB 8
#define NN 4096
#define DD 768
#define EE 8
#define ES 16
#define FF 3072
#define NTOK (BB*NN)     /* 32768 */
#define PSZ  (NTOK*ES)   /* 524288 */

typedef unsigned long long ull;

/* ---------------- scratch (allocation-free, 16B-aligned) ---------------- */
__device__ __align__(16) float  g_part[3*PSZ];     /* k1 logits partials */
__device__ __align__(16) float  g_logits[PSZ];
__device__ __align__(16) float2 g_cpart[128*16];   /* per-(chunk,slot) combine partials */
__device__ __align__(16) float  g_xsp[256*16*768]; /* k3 partials [b*32+c][slot][d] */
__device__ __align__(16) float  g_h1p[8*EE*ES*FF]; /* k4 partials [dc*8+e][r][f] */
__device__ __align__(16) float  g_ysp[32*EE*ES*DD];/* k5 partials [kc*8+e][r][d] */
__device__ __align__(16) float  g_ys[BB*ES*DD];

/* ---------------- f32x2 helpers ---------------- */
__device__ __forceinline__ ull fma2(ull a, ull b, ull c) {
    ull d; asm("fma.rn.f32x2 %0, %1, %2, %3;" : "=l"(d) : "l"(a), "l"(b), "l"(c)); return d;
}
__device__ __forceinline__ ull dup2(float x) {
    ull r; asm("mov.b64 %0, {%1, %1};" : "=l"(r) : "f"(x)); return r;
}
__device__ __forceinline__ float2 unpack2(ull a) {
    float2 t; asm("mov.b64 {%0, %1}, %2;" : "=f"(t.x), "=f"(t.y) : "l"(a)); return t;
}
__device__ __forceinline__ float gelu_exact(float v) {
    return 0.5f * v * (1.0f + erff(v * 0.70710678118654752440f));
}
__device__ __forceinline__ float warp_max(float v) {
#pragma unroll
    for (int o = 16; o; o >>= 1) v = fmaxf(v, __shfl_xor_sync(0xffffffffu, v, o));
    return v;
}
__device__ __forceinline__ float warp_sum(float v) {
#pragma unroll
    for (int o = 16; o; o >>= 1) v += __shfl_xor_sync(0xffffffffu, v, o);
    return v;
}

/* ================ K1: logits partials  grid(64 tokblocks, 3 kchunks of 256), 256 thr ===== */
__global__ void __launch_bounds__(256) k1_logits(const float* __restrict__ x,
                                                 const float* __restrict__ phi) {
    extern __shared__ float sm[];
    float* xsh = sm;              /* [512][33] pitch-33 */
    float* ph  = sm + 512 * 33;   /* [256][16] */
    const int tid = threadIdx.x;
    const int tokBase = blockIdx.x * 512;
    const int k0 = blockIdx.y * 256;

    for (int i = tid; i < 1024; i += 256)
        ((float4*)ph)[i] = ((const float4*)(phi + (size_t)k0 * ES))[i];

    ull acc[2][8];
#pragma unroll
    for (int p = 0; p < 2; p++)
#pragma unroll
        for (int j = 0; j < 8; j++) acc[p][j] = 0ull;

    for (int sc = 0; sc < 8; sc++) {
        const int kk0 = k0 + sc * 32;
        __syncthreads();
#pragma unroll
        for (int i = 0; i < 16; i++) {
            int idx = tid + 256 * i;
            int t = idx >> 3, q = idx & 7;
            float4 v = *(const float4*)(x + (size_t)(tokBase + t) * DD + kk0 + q * 4);
            float* dst = &xsh[t * 33 + q * 4];   /* scalar STS: pitch-33 alignment */
            dst[0] = v.x; dst[1] = v.y; dst[2] = v.z; dst[3] = v.w;
        }
        __syncthreads();
#pragma unroll 4
        for (int kk = 0; kk < 32; kk++) {
            ull xd0 = dup2(xsh[tid * 33 + kk]);
            ull xd1 = dup2(xsh[(tid + 256) * 33 + kk]);
            const float* pr = &ph[(sc * 32 + kk) * ES];
#pragma unroll
            for (int j = 0; j < 8; j++) {
                ull p2 = *(const ull*)&pr[2 * j];
                acc[0][j] = fma2(xd0, p2, acc[0][j]);
                acc[1][j] = fma2(xd1, p2, acc[1][j]);
            }
        }
    }
    float* outb = g_part + (size_t)blockIdx.y * PSZ;
#pragma unroll
    for (int p = 0; p < 2; p++) {
        int t = tokBase + tid + 256 * p;
        float4* o = (float4*)&outb[(size_t)t * ES];
#pragma unroll
        for (int j2 = 0; j2 < 4; j2++) {
            float2 a = unpack2(acc[p][2 * j2]);
            float2 b = unpack2(acc[p][2 * j2 + 1]);
            o[j2] = make_float4(a.x, a.y, b.x, b.y);
        }
    }
}

/* ================ K2a: sum 3 partials -> logits; combine partial-reduce ===== */
__global__ void __launch_bounds__(256) k2a_dispatch() {
    __shared__ float2 wred[8 * 16];
    const int tid = threadIdx.x;
    const int t = blockIdx.x * 256 + tid;
    const int wid = tid >> 5, lane = tid & 31;
    float v[16];
#pragma unroll
    for (int i = 0; i < 16; i++) v[i] = 0.0f;
#pragma unroll
    for (int c = 0; c < 3; c++) {
        const float4* p = (const float4*)(g_part + (size_t)c * PSZ + (size_t)t * ES);
#pragma unroll
        for (int i = 0; i < 4; i++) {
            float4 a = p[i];
            v[4*i+0] += a.x; v[4*i+1] += a.y; v[4*i+2] += a.z; v[4*i+3] += a.w;
        }
    }
    float4* lo = (float4*)&g_logits[(size_t)t * ES];
#pragma unroll
    for (int i = 0; i < 4; i++)
        lo[i] = make_float4(v[4*i], v[4*i+1], v[4*i+2], v[4*i+3]);
#pragma unroll
    for (int sl = 0; sl < 16; sl++) {
        float wm = warp_max(v[sl]);
        float ws = warp_sum(expf(v[sl] - wm));
        if (lane == 0) wred[wid * 16 + sl] = make_float2(wm, ws);
    }
    __syncthreads();
    if (tid < 16) {
        float gm = -1e30f;
#pragma unroll
        for (int w = 0; w < 8; w++) gm = fmaxf(gm, wred[w * 16 + tid].x);
        float gs = 0.0f;
#pragma unroll
        for (int w = 0; w < 8; w++) {
            float2 p = wred[w * 16 + tid];
            gs += expf(p.x - gm) * p.y;
        }
        g_cpart[blockIdx.x * 16 + tid] = make_float2(gm, gs);
    }
}

/* ================ K3: xs partials, pipelined  grid(32,8), 192 thr, 2 CTAs/SM ===== */
__global__ void __launch_bounds__(192, 2) k3_xs(const float* __restrict__ x) {
    __shared__ float2 dsh[128 * 16];
    const int chunk = blockIdx.x, b = blockIdx.y, tid = threadIdx.x;
    const int n0 = chunk * 128;
    if (tid < 128) {
        const float4* lp = (const float4*)&g_logits[(size_t)(b * NN + n0 + tid) * ES];
        float v[16];
#pragma unroll
        for (int i = 0; i < 4; i++) {
            float4 a = lp[i];
            v[4*i] = a.x; v[4*i+1] = a.y; v[4*i+2] = a.z; v[4*i+3] = a.w;
        }
        float m = v[0];
#pragma unroll
        for (int i = 1; i < 16; i++) m = fmaxf(m, v[i]);
        float ex[16], s = 0.0f;
#pragma unroll
        for (int i = 0; i < 16; i++) { ex[i] = expf(v[i] - m); s += ex[i]; }
        float inv = 1.0f / s;
        float2* dr = &dsh[tid * 16];
#pragma unroll
        for (int i = 0; i < 16; i++) { float w = ex[i] * inv; dr[i] = make_float2(w, w); }
    }
    __syncthreads();
    ull acc[16][2];
#pragma unroll
    for (int s = 0; s < 16; s++) { acc[s][0] = 0ull; acc[s][1] = 0ull; }
    const float* xb = x + (size_t)(b * NN + n0) * DD + tid * 4;
    float4 xv[2][4];
#pragma unroll
    for (int u = 0; u < 4; u++) xv[0][u] = *(const float4*)(xb + (size_t)u * DD);
#pragma unroll
    for (int g = 0; g < 128; g += 4) {
        const int cur = (g >> 2) & 1, nxt = cur ^ 1;
        if (g + 4 < 128) {
#pragma unroll
            for (int u = 0; u < 4; u++)
                xv[nxt][u] = *(const float4*)(xb + (size_t)(g + 4 + u) * DD);
        }
#pragma unroll
        for (int u = 0; u < 4; u++) {
            ull l = *(ull*)&xv[cur][u].x, h = *(ull*)&xv[cur][u].z;
            const float2* dr = &dsh[(g + u) * 16];
#pragma unroll
            for (int s = 0; s < 16; s++) {
                ull c = *(const ull*)&dr[s];
                acc[s][0] = fma2(c, l, acc[s][0]);
                acc[s][1] = fma2(c, h, acc[s][1]);
            }
        }
    }
    float* op = g_xsp + (size_t)(b * 32 + chunk) * 16 * DD + tid * 4;
#pragma unroll
    for (int s = 0; s < 16; s++) {
        float2 a = unpack2(acc[s][0]), c = unpack2(acc[s][1]);
        *(float4*)(op + (size_t)s * DD) = make_float4(a.x, a.y, c.x, c.y);
    }
}

/* ================ K4: FFN1, pipelined weight stream
   grid(6 ftiles of 512, 8 e, 8 dchunks), 128 thr, 4 CTAs/SM ===== */
__global__ void __launch_bounds__(128, 4) k4_ffn1(const float* __restrict__ w1) {
    __shared__ float2 xd[16][104];    /* [r][ddv] dup-pairs, pitch 832B */
    const int ft = blockIdx.x, e = blockIdx.y, dc = blockIdx.z, tid = threadIdx.x;
    const int dk0 = dc * 96;
    for (int i = tid; i < 1536; i += 128) {
        int r = i / 96, ddv = i - r * 96;
        const float* p = g_xsp + ((size_t)((r >> 1) * 32) * 16 + e * 2 + (r & 1)) * DD
                       + dk0 + ddv;
        float s = 0.0f;
#pragma unroll
        for (int cb = 0; cb < 2; cb++) {
            float tv[16];
#pragma unroll
            for (int c = 0; c < 16; c++) tv[c] = p[(size_t)(cb * 16 + c) * (16 * DD)];
#pragma unroll
            for (int c = 0; c < 16; c++) s += tv[c];
        }
        xd[r][ddv] = make_float2(s, s);
    }
    __syncthreads();
    const int f = ft * 512 + tid * 4;
    const float* wp = w1 + (size_t)e * DD * FF + (size_t)dk0 * FF + f;
    ull acc[16][2];
#pragma unroll
    for (int r = 0; r < 16; r++) { acc[r][0] = 0ull; acc[r][1] = 0ull; }
    float4 wv[2][4];
#pragma unroll
    for (int u = 0; u < 4; u++) wv[0][u] = *(const float4*)(wp + (size_t)u * FF);
#pragma unroll
    for (int d = 0; d < 96; d += 4) {
        const int cur = (d >> 2) & 1, nxt = cur ^ 1;
        if (d + 4 < 96) {
#pragma unroll
            for (int u = 0; u < 4; u++)
                wv[nxt][u] = *(const float4*)(wp + (size_t)(d + 4 + u) * FF);
        }
#pragma unroll
        for (int r = 0; r < 16; r++) {
#pragma unroll
            for (int q = 0; q < 2; q++) {
                float4 xq = *(const float4*)&xd[r][d + 2 * q];   /* broadcast LDS.128 */
                ull c0 = *(ull*)&xq.x, c1 = *(ull*)&xq.z;
                acc[r][0] = fma2(c0, *(ull*)&wv[cur][2*q].x,   acc[r][0]);
                acc[r][1] = fma2(c0, *(ull*)&wv[cur][2*q].z,   acc[r][1]);
                acc[r][0] = fma2(c1, *(ull*)&wv[cur][2*q+1].x, acc[r][0]);
                acc[r][1] = fma2(c1, *(ull*)&wv[cur][2*q+1].z, acc[r][1]);
            }
        }
    }
    float* op = g_h1p + (size_t)(dc * 8 + e) * 16 * FF + f;
#pragma unroll
    for (int r = 0; r < 16; r++) {
        float2 a = unpack2(acc[r][0]), c = unpack2(acc[r][1]);
        *(float4*)(op + (size_t)r * FF) = make_float4(a.x, a.y, c.x, c.y);
    }
}

/* ================ K5: FFN2, pipelined weight stream
   grid(32 kchunks of 96, 8 e, 2 dtiles of 384), 96 thr, 5 CTAs/SM ===== */
__global__ void __launch_bounds__(96, 5) k5_ffn2(const float* __restrict__ w2,
                                                 const float* __restrict__ b1) {
    __shared__ float2 hd[16][104];    /* [r][kk] dup-pairs, pitch 832B */
    const int kc = blockIdx.x, e = blockIdx.y, dt = blockIdx.z, tid = threadIdx.x;
    const int k0 = kc * 96;
    for (int i = tid; i < 1536; i += 96) {
        int r = i / 96, kk = i - r * 96;
        int fidx = k0 + kk;
        const float* p = g_h1p + ((size_t)e * 16 + r) * FF + fidx;
        float s = 0.0f;
        float tv[8];
#pragma unroll
        for (int c = 0; c < 8; c++) tv[c] = p[(size_t)c * (8 * 16 * FF)];
#pragma unroll
        for (int c = 0; c < 8; c++) s += tv[c];
        s = gelu_exact(s + b1[e * FF + fidx]);
        hd[r][kk] = make_float2(s, s);
    }
    __syncthreads();
    const int d = dt * 384 + tid * 4;
    const float* wp = w2 + (size_t)e * FF * DD + (size_t)k0 * DD + d;
    ull acc[16][2];
#pragma unroll
    for (int r = 0; r < 16; r++) { acc[r][0] = 0ull; acc[r][1] = 0ull; }
    float4 wv[2][4];
#pragma unroll
    for (int u = 0; u < 4; u++) wv[0][u] = *(const float4*)(wp + (size_t)u * DD);
#pragma unroll
    for (int kk = 0; kk < 96; kk += 4) {
        const int cur = (kk >> 2) & 1, nxt = cur ^ 1;
        if (kk + 4 < 96) {
#pragma unroll
            for (int u = 0; u < 4; u++)
                wv[nxt][u] = *(const float4*)(wp + (size_t)(kk + 4 + u) * DD);
        }
#pragma unroll
        for (int r = 0; r < 16; r++) {
#pragma unroll
            for (int q = 0; q < 2; q++) {
                float4 xq = *(const float4*)&hd[r][kk + 2 * q];  /* broadcast LDS.128 */
                ull c0 = *(ull*)&xq.x, c1 = *(ull*)&xq.z;
                acc[r][0] = fma2(c0, *(ull*)&wv[cur][2*q].x,   acc[r][0]);
                acc[r][1] = fma2(c0, *(ull*)&wv[cur][2*q].z,   acc[r][1]);
                acc[r][0] = fma2(c1, *(ull*)&wv[cur][2*q+1].x, acc[r][0]);
                acc[r][1] = fma2(c1, *(ull*)&wv[cur][2*q+1].z, acc[r][1]);
            }
        }
    }
    float* op = g_ysp + (size_t)(kc * 8 + e) * 16 * DD + d;
#pragma unroll
    for (int r = 0; r < 16; r++) {
        float2 a = unpack2(acc[r][0]), c = unpack2(acc[r][1]);
        *(float4*)(op + (size_t)r * DD) = make_float4(a.x, a.y, c.x, c.y);
    }
}

/* ================ K5r: reduce 32 kchunks + bias -> g_ys  grid(192), 256 thr ===== */
__global__ void __launch_bounds__(256) k5r_reduce(const float* __restrict__ b2) {
    int o2 = blockIdx.x * 256 + threadIdx.x;    /* 49152 float2 outputs */
    int d2 = o2 % 384, rest = o2 / 384;
    int sl = rest & 15, b = rest >> 4;
    int e = sl >> 1;
    int r = b * 2 + (sl & 1);
    const float2* p = (const float2*)(g_ysp + ((size_t)e * 16 + r) * DD) + d2;
    float sx = 0.f, sy = 0.f;
#pragma unroll
    for (int cb = 0; cb < 2; cb++) {
        float2 tv[16];
#pragma unroll
        for (int c = 0; c < 16; c++)
            tv[c] = p[(size_t)(cb * 16 + c) * (8 * 16 * 384)];
#pragma unroll
        for (int c = 0; c < 16; c++) { sx += tv[c].x; sy += tv[c].y; }
    }
    float2 bv = ((const float2*)b2)[e * 384 + d2];
    ((float2*)g_ys)[(size_t)(b * 16 + sl) * 384 + d2] = make_float2(sx + bv.x, sy + bv.y);
}

/* ================ K6: combine norm + y = comb @ ys  grid(64,8), 256 thr ===== */
__global__ void __launch_bounds__(256) k6_out(float* __restrict__ y) {
    __shared__ float2 cms_sh[16];
    __shared__ float csh[64 * ES];
    const int chunk = blockIdx.x, b = blockIdx.y, tid = threadIdx.x;
    ull ysr[8][3];
#pragma unroll
    for (int j = 0; j < 8; j++)
#pragma unroll
        for (int dd = 0; dd < 3; dd++) {
            int d = tid + 256 * dd;
            float a = g_ys[(size_t)(b * 16 + 2 * j) * DD + d];
            float c = g_ys[(size_t)(b * 16 + 2 * j + 1) * DD + d];
            ull r; asm("mov.b64 %0, {%1, %2};" : "=l"(r) : "f"(a), "f"(c));
            ysr[j][dd] = r;
        }
    if (tid < 16) {
        float gm = -1e30f;
#pragma unroll
        for (int c = 0; c < 16; c++) gm = fmaxf(gm, g_cpart[(b * 16 + c) * 16 + tid].x);
        float gs = 0.0f;
#pragma unroll
        for (int c = 0; c < 16; c++) {
            float2 p = g_cpart[(b * 16 + c) * 16 + tid];
            gs += expf(p.x - gm) * p.y;
        }
        cms_sh[tid] = make_float2(gm, 1.0f / gs);
    }
    ((float4*)csh)[tid] = ((const float4*)&g_logits[(size_t)(b * NN + chunk * 64) * ES])[tid];
    __syncthreads();
    {
        int sl = (tid * 4) & 15;
        float4 v = ((float4*)csh)[tid];
        v.x = expf(v.x - cms_sh[sl+0].x) * cms_sh[sl+0].y;
        v.y = expf(v.y - cms_sh[sl+1].x) * cms_sh[sl+1].y;
        v.z = expf(v.z - cms_sh[sl+2].x) * cms_sh[sl+2].y;
        v.w = expf(v.w - cms_sh[sl+3].x) * cms_sh[sl+3].y;
        __syncthreads();
        ((float4*)csh)[tid] = v;
    }
    __syncthreads();
#pragma unroll 2
    for (int tok = 0; tok < 64; tok++) {
        ull c2[8];
#pragma unroll
        for (int j = 0; j < 8; j++) c2[j] = *(const ull*)&csh[tok * ES + 2 * j];
        float* yo = y + (size_t)(b * NN + chunk * 64 + tok) * DD + tid;
#pragma unroll
        for (int dd = 0; dd < 3; dd++) {
            ull a = 0ull;
#pragma unroll
            for (int j = 0; j < 8; j++) a = fma2(c2[j], ysr[j][dd], a);
            float2 t = unpack2(a);
            yo[256 * dd] = t.x + t.y;
        }
    }
}

/* ---------------- launch ---------------- */
extern "C" void kernel_launch(void* const* d_in, const int* in_sizes, int n_in,
                              void* d_out, int out_size) {
    const float* x   = (const float*)d_in[0];
    const float* phi = (const float*)d_in[1];
    const float* w1  = (const float*)d_in[2];
    const float* b1  = (const float*)d_in[3];
    const float* w2  = (const float*)d_in[4];
    const float* b2  = (const float*)d_in[5];
    float* y = (float*)d_out;

    cudaFuncSetAttribute(k1_logits, cudaFuncAttributeMaxDynamicSharedMemorySize, 86016);

    k1_logits<<<dim3(64, 3), 256, 83968>>>(x, phi);
    k2a_dispatch<<<128, 256>>>();
    k3_xs<<<dim3(32, 8), 192>>>(x);
    k4_ffn1<<<dim3(6, 8, 8), 128>>>(w1);
    k5_ffn2<<<dim3(32, 8, 2), 96>>>(w2, b1);
    k5r_reduce<<<192, 256>>>(b2);
    k6_out<<<dim3(64, 8), 256>>>(y);
}